// round 6
// baseline (speedup 1.0000x reference)
#include <cuda_runtime.h>

#define N_TOT 6016
#define NBLK  592          // 4 blocks/SM x 148 SMs: all resident -> barrier is safe
#define NMLP  376          // node groups of 16 -> 6016 nodes
#define NTILE 9176

// Static shape tables: sizes g = 256 + 16*g, g in [0,16)
__constant__ int c_node_start[17] = {
    0,256,528,816,1120,1440,1776,2128,2496,2880,3280,3696,4128,4576,5040,5520,6016};
__constant__ long long c_pair_start[17] = {
    0,65536,139520,222464,314880,417280,530176,654080,789504,936960,
    1096960,1270016,1456640,1657344,1872640,2103040,2349056};
__constant__ int c_tile_start[17] = {
    0,256,545,869,1230,1630,2071,2555,3084,3660,4285,4961,5690,6474,7315,8215,9176};

// staged per-node MLP output t[N_TOT][32]
__device__ float g_t[N_TOT * 32];

// barrier state (zero-initialized once; reset in-kernel every launch)
__device__ int g_arrive = 0;
__device__ int g_passed = 0;

// ---------------------------------------------------------------------------
// Fused kernel.
// Phase 1 (blocks 0..375): per-node MLP t = relu(ape@W1+b1)@W2+b2 for this
//   block's 16 nodes (16 threads/node, conflict-free two-stage, as R5).
// Barrier: L2 atomic counter; all 592 blocks are co-resident by construction.
// Phase 2 (all blocks): stride over 9176 16x16 pair tiles,
//   out[ps + i*nb + j][:] = t[ns+i][:] + t[ns+j][:].
// ---------------------------------------------------------------------------
__global__ __launch_bounds__(256, 4)
void fused_kernel(const float* __restrict__ ape,
                  const float* __restrict__ W1, const float* __restrict__ b1,
                  const float* __restrict__ W2, const float* __restrict__ b2,
                  float* __restrict__ out) {
    __shared__ __align__(16) union {
        struct {
            float W1[16 * 64];
            float W2[64 * 32];
            float b1[64];
            float b2[32];
            float in[16 * 16];
            float h[16 * 64];
        } m;
        struct {
            float4 ti[16 * 8];
            float4 tj[16 * 8];
        } p;
    } sm;

    int tid = threadIdx.x;
    int bid = blockIdx.x;

    // ---------------- Phase 1: MLP for node group bid (if bid < 376) --------
    if (bid < NMLP) {
        for (int k = tid; k < 16 * 64; k += 256) sm.m.W1[k] = W1[k];
        for (int k = tid; k < 64 * 32; k += 256) sm.m.W2[k] = W2[k];
        if (tid < 64) sm.m.b1[tid] = b1[tid];
        if (tid < 32) sm.m.b2[tid] = b2[tid];
        if (tid < 64) ((float4*)sm.m.in)[tid] = ((const float4*)ape)[bid * 64 + tid];
        __syncthreads();

        int nl = tid >> 4;             // node within group, 0..15
        int p  = tid & 15;
        int n  = bid * 16 + nl;

        // Stage A: hidden values 4p..4p+3 (conflict-free float4 reads)
        float v0 = sm.m.b1[4 * p + 0], v1 = sm.m.b1[4 * p + 1];
        float v2 = sm.m.b1[4 * p + 2], v3 = sm.m.b1[4 * p + 3];
        {
            const float4* w1v = (const float4*)sm.m.W1;
            const float*  ain = sm.m.in + nl * 16;
#pragma unroll
            for (int k = 0; k < 16; k++) {
                float  av = ain[k];
                float4 w  = w1v[k * 16 + p];
                v0 = fmaf(av, w.x, v0);
                v1 = fmaf(av, w.y, v1);
                v2 = fmaf(av, w.z, v2);
                v3 = fmaf(av, w.w, v3);
            }
        }
        float4 hv;
        hv.x = fmaxf(v0, 0.0f); hv.y = fmaxf(v1, 0.0f);
        hv.z = fmaxf(v2, 0.0f); hv.w = fmaxf(v3, 0.0f);
        ((float4*)sm.m.h)[nl * 16 + p] = hv;
        __syncthreads();

        // Stage B: outputs 2p, 2p+1 (conflict-free float2 reads)
        float o0 = sm.m.b2[2 * p + 0], o1 = sm.m.b2[2 * p + 1];
        {
            const float4* h4p = (const float4*)(sm.m.h + nl * 64);
            const float2* w2v = (const float2*)sm.m.W2;
#pragma unroll
            for (int q = 0; q < 16; q++) {
                float4 h4 = h4p[q];
                float2 wa = w2v[(q * 4 + 0) * 16 + p];
                float2 wb = w2v[(q * 4 + 1) * 16 + p];
                float2 wc = w2v[(q * 4 + 2) * 16 + p];
                float2 wd = w2v[(q * 4 + 3) * 16 + p];
                o0 = fmaf(h4.x, wa.x, o0); o1 = fmaf(h4.x, wa.y, o1);
                o0 = fmaf(h4.y, wb.x, o0); o1 = fmaf(h4.y, wb.y, o1);
                o0 = fmaf(h4.z, wc.x, o0); o1 = fmaf(h4.z, wc.y, o1);
                o0 = fmaf(h4.w, wd.x, o0); o1 = fmaf(h4.w, wd.y, o1);
            }
        }
        float2 r2; r2.x = o0; r2.y = o1;
        *(float2*)(g_t + n * 32 + p * 2) = r2;

        // release: make g_t stores visible, then arrive
        __threadfence();
        __syncthreads();
        if (tid == 0) atomicAdd(&g_arrive, 1);
    }

    // ---------------- Global barrier: wait for all 376 MLP groups ----------
    if (tid == 0) {
        while (atomicAdd(&g_arrive, 0) < NMLP) __nanosleep(32);
    }
    __syncthreads();
    __threadfence();

    // ---------------- Phase 2: pair tiles, strided ------------------------
    const float4* tp = (const float4*)g_t;
    float4* op = (float4*)out;
    int l    = tid & 127;        // j*8+q within a 16-row group
    int half = tid >> 7;         // which ii parity this thread covers
    int q    = l & 7;

    for (int blk = bid; blk < NTILE; blk += NBLK) {
        int b = 0;
#pragma unroll
        for (int g = 1; g < 16; g++)
            if (blk >= c_tile_start[g]) b = g;

        int lt  = blk - c_tile_start[b];
        int tpr = 16 + b;            // tiles per row = n_b/16
        int nb  = tpr << 4;          // n_b
        int ti  = lt / tpr;
        int tj  = lt - ti * tpr;
        int ns  = c_node_start[b];
        long long ps = c_pair_start[b];

        __syncthreads();             // smem reuse guard (and union handoff)
        if (tid < 128) {
            sm.p.ti[tid] = tp[(ns + ti * 16) * 8 + tid];
        } else {
            sm.p.tj[tid - 128] = tp[(ns + tj * 16) * 8 + (tid - 128)];
        }
        __syncthreads();

        float4 vj = sm.p.tj[l];
        long long rowbase = ps + (long long)(ti * 16) * nb + tj * 16;

#pragma unroll
        for (int step = 0; step < 8; step++) {
            int ii = step * 2 + half;
            float4 vi = sm.p.ti[ii * 8 + q];
            float4 v;
            v.x = vi.x + vj.x; v.y = vi.y + vj.y;
            v.z = vi.z + vj.z; v.w = vi.w + vj.w;
            op[(rowbase + (long long)ii * nb) * 8 + l] = v;   // 2KB wavefront
        }
    }

    // ---------------- Reset barrier state for the next replay -------------
    __syncthreads();
    if (tid == 0) {
        int r = atomicAdd(&g_passed, 1);
        if (r == NBLK - 1) {          // last block: everyone passed the barrier
            atomicExch(&g_arrive, 0);
            atomicExch(&g_passed, 0);
        }
    }
}

// ---------------------------------------------------------------------------
extern "C" void kernel_launch(void* const* d_in, const int* in_sizes, int n_in,
                              void* d_out, int out_size) {
    const float* ape = (const float*)d_in[0];
    const float* W1  = (const float*)d_in[1];
    const float* b1  = (const float*)d_in[2];
    const float* W2  = (const float*)d_in[3];
    const float* b2  = (const float*)d_in[4];
    float* out = (float*)d_out;

    fused_kernel<<<NBLK, 256>>>(ape, W1, b1, W2, b2, out);
}

// round 7
// speedup vs baseline: 1.0233x; 1.0233x over previous
#include <cuda_runtime.h>

#define N_TOT 6016
#define NMLP  376          // 16-node groups
#define NTILE 9176

// Static shape tables: sizes g = 256 + 16*g, g in [0,16)
__constant__ int c_node_start[17] = {
    0,256,528,816,1120,1440,1776,2128,2496,2880,3280,3696,4128,4576,5040,5520,6016};
__constant__ long long c_pair_start[17] = {
    0,65536,139520,222464,314880,417280,530176,654080,789504,936960,
    1096960,1270016,1456640,1657344,1872640,2103040,2349056};
__constant__ int c_tile_start[17] = {
    0,256,545,869,1230,1630,2071,2555,3084,3660,4285,4961,5690,6474,7315,8215,9176};

// staged per-node MLP output t[N_TOT][32]
__device__ float g_t[N_TOT * 32];

// per-group ready flags + completion counter (reset in-kernel each launch)
__device__ int g_flag[NMLP];   // zero-initialized
__device__ int g_done = 0;

// ---------------------------------------------------------------------------
// Fused single kernel, pair-shaped grid (9176 blocks).
//   Blocks 0..375: compute MLP t for node group bid (16 nodes), release flag.
//   All blocks:    process pair tile bid, spin-waiting on the 2 group flags.
// Deadlock-free: launch_bounds(256,6) -> wave 1 >= 888 blocks, contains all
// 376 producers; consumers' spins end when producers (co-resident) finish.
// ---------------------------------------------------------------------------
__global__ __launch_bounds__(256, 6)
void fused_kernel(const float* __restrict__ ape,
                  const float* __restrict__ W1, const float* __restrict__ b1,
                  const float* __restrict__ W2, const float* __restrict__ b2,
                  float* __restrict__ out) {
    __shared__ __align__(16) union {
        struct {
            float W1[16 * 64];
            float W2[64 * 32];
            float b1[64];
            float b2[32];
            float in[16 * 16];
            float h[16 * 64];
        } m;
        struct {
            float4 ti[16 * 8];
            float4 tj[16 * 8];
        } p;
    } sm;
    __shared__ int s_last;

    int tid = threadIdx.x;
    int bid = blockIdx.x;

    // ================= Phase 1: MLP (producers only) =======================
    if (bid < NMLP) {
        for (int k = tid; k < 16 * 64; k += 256) sm.m.W1[k] = W1[k];
        for (int k = tid; k < 64 * 32; k += 256) sm.m.W2[k] = W2[k];
        if (tid < 64) sm.m.b1[tid] = b1[tid];
        if (tid < 32) sm.m.b2[tid] = b2[tid];
        if (tid < 64) ((float4*)sm.m.in)[tid] = ((const float4*)ape)[bid * 64 + tid];
        __syncthreads();

        int nl = tid >> 4;             // node within group, 0..15
        int p  = tid & 15;
        int n  = bid * 16 + nl;

        // Stage A: hidden values 4p..4p+3 (conflict-free float4 reads)
        float v0 = sm.m.b1[4 * p + 0], v1 = sm.m.b1[4 * p + 1];
        float v2 = sm.m.b1[4 * p + 2], v3 = sm.m.b1[4 * p + 3];
        {
            const float4* w1v = (const float4*)sm.m.W1;
            const float*  ain = sm.m.in + nl * 16;
#pragma unroll
            for (int k = 0; k < 16; k++) {
                float  av = ain[k];
                float4 w  = w1v[k * 16 + p];
                v0 = fmaf(av, w.x, v0);
                v1 = fmaf(av, w.y, v1);
                v2 = fmaf(av, w.z, v2);
                v3 = fmaf(av, w.w, v3);
            }
        }
        float4 hv;
        hv.x = fmaxf(v0, 0.0f); hv.y = fmaxf(v1, 0.0f);
        hv.z = fmaxf(v2, 0.0f); hv.w = fmaxf(v3, 0.0f);
        ((float4*)sm.m.h)[nl * 16 + p] = hv;
        __syncthreads();

        // Stage B: outputs 2p, 2p+1 (conflict-free float2 reads)
        float o0 = sm.m.b2[2 * p + 0], o1 = sm.m.b2[2 * p + 1];
        {
            const float4* h4p = (const float4*)(sm.m.h + nl * 64);
            const float2* w2v = (const float2*)sm.m.W2;
#pragma unroll
            for (int q = 0; q < 16; q++) {
                float4 h4 = h4p[q];
                float2 wa = w2v[(q * 4 + 0) * 16 + p];
                float2 wb = w2v[(q * 4 + 1) * 16 + p];
                float2 wc = w2v[(q * 4 + 2) * 16 + p];
                float2 wd = w2v[(q * 4 + 3) * 16 + p];
                o0 = fmaf(h4.x, wa.x, o0); o1 = fmaf(h4.x, wa.y, o1);
                o0 = fmaf(h4.y, wb.x, o0); o1 = fmaf(h4.y, wb.y, o1);
                o0 = fmaf(h4.z, wc.x, o0); o1 = fmaf(h4.z, wc.y, o1);
                o0 = fmaf(h4.w, wd.x, o0); o1 = fmaf(h4.w, wd.y, o1);
            }
        }
        float2 r2; r2.x = o0; r2.y = o1;
        *(float2*)(g_t + n * 32 + p * 2) = r2;

        // release this group's flag
        __threadfence();
        __syncthreads();               // all g_t stores of the group done
        if (tid == 0) atomicExch(&g_flag[bid], 1);
        __syncthreads();               // union handoff (smem reuse below)
    }

    // ================= Phase 2: this block's pair tile =====================
    int blk = bid;
    int b = 0;
#pragma unroll
    for (int g = 1; g < 16; g++)
        if (blk >= c_tile_start[g]) b = g;

    int lt  = blk - c_tile_start[b];
    int tpr = 16 + b;                  // tiles per row = n_b/16
    int nb  = tpr << 4;                // n_b
    int ti  = lt / tpr;
    int tj  = lt - ti * tpr;
    int ns  = c_node_start[b];
    long long ps = c_pair_start[b];
    int g0  = (ns >> 4) + ti;          // producer group of the i-rows
    int g1  = (ns >> 4) + tj;          // producer group of the j-rows

    // wait for the two producer groups (first wave only; later waves: 1 atomic)
    if (tid == 0) {
        while (atomicAdd(&g_flag[g0], 0) == 0) __nanosleep(20);
    } else if (tid == 1) {
        while (atomicAdd(&g_flag[g1], 0) == 0) __nanosleep(20);
    }
    __syncthreads();
    __threadfence();                   // acquire: order g_t reads after flags

    const float4* tp = (const float4*)g_t;
    if (tid < 128) {
        sm.p.ti[tid] = tp[(ns + ti * 16) * 8 + tid];
    } else {
        sm.p.tj[tid - 128] = tp[(ns + tj * 16) * 8 + (tid - 128)];
    }
    __syncthreads();

    float4* op = (float4*)out;
    int l    = tid & 127;              // j*8+q within a 16-row group
    int half = tid >> 7;
    int q    = l & 7;

    float4 vj = sm.p.tj[l];
    long long rowbase = ps + (long long)(ti * 16) * nb + tj * 16;

#pragma unroll
    for (int step = 0; step < 8; step++) {
        int ii = step * 2 + half;
        float4 vi = sm.p.ti[ii * 8 + q];
        float4 v;
        v.x = vi.x + vj.x; v.y = vi.y + vj.y;
        v.z = vi.z + vj.z; v.w = vi.w + vj.w;
        op[(rowbase + (long long)ii * nb) * 8 + l] = v;   // 2KB wavefront
    }

    // ================= Reset state for next replay =========================
    __syncthreads();
    if (tid == 0) {
        s_last = (atomicAdd(&g_done, 1) == NTILE - 1) ? 1 : 0;
    }
    __syncthreads();
    if (s_last) {
        for (int k = tid; k < NMLP; k += 256) g_flag[k] = 0;
        if (tid == 0) atomicExch(&g_done, 0);
    }
}

// ---------------------------------------------------------------------------
extern "C" void kernel_launch(void* const* d_in, const int* in_sizes, int n_in,
                              void* d_out, int out_size) {
    const float* ape = (const float*)d_in[0];
    const float* W1  = (const float*)d_in[1];
    const float* b1  = (const float*)d_in[2];
    const float* W2  = (const float*)d_in[3];
    const float* b2  = (const float*)d_in[4];
    float* out = (float*)d_out;

    fused_kernel<<<NTILE, 256>>>(ape, W1, b1, W2, b2, out);
}

// round 8
// speedup vs baseline: 1.1438x; 1.1179x over previous
#include <cuda_runtime.h>

#define N_TOT 6016
#define NMLP  376          // 16-node groups
#define NTILE 9176

// Static shape tables: sizes g = 256 + 16*g, g in [0,16)
__constant__ int c_node_start[17] = {
    0,256,528,816,1120,1440,1776,2128,2496,2880,3280,3696,4128,4576,5040,5520,6016};
__constant__ long long c_pair_start[17] = {
    0,65536,139520,222464,314880,417280,530176,654080,789504,936960,
    1096960,1270016,1456640,1657344,1872640,2103040,2349056};
__constant__ int c_tile_start[17] = {
    0,256,545,869,1230,1630,2071,2555,3084,3660,4285,4961,5690,6474,7315,8215,9176};

// staged per-node MLP output t[N_TOT][32]
__device__ float g_t[N_TOT * 32];

// per-group ready flags + completion counter (reset in-kernel each launch)
__device__ int g_flag[NMLP];   // zero-initialized
__device__ int g_done = 0;

__device__ __forceinline__ int ld_acquire_gpu(const int* p) {
    int v;
    asm volatile("ld.acquire.gpu.b32 %0, [%1];" : "=r"(v) : "l"(p) : "memory");
    return v;
}

// ---------------------------------------------------------------------------
// Fused single kernel, pair-shaped grid (9176 blocks), 8 blocks/SM.
//   Blocks 0..375: compute MLP t for node group bid (16 nodes), release flag.
//   All blocks:    process pair tile bid, acquire-spinning on 2 group flags.
// Deadlock-free: launch_bounds(256,8) -> wave 1 = 1184 blocks >= 376 producers.
// ---------------------------------------------------------------------------
__global__ __launch_bounds__(256, 8)
void fused_kernel(const float* __restrict__ ape,
                  const float* __restrict__ W1, const float* __restrict__ b1,
                  const float* __restrict__ W2, const float* __restrict__ b2,
                  float* __restrict__ out) {
    __shared__ __align__(16) union {
        struct {
            float W1[16 * 64];
            float W2[64 * 32];
            float b1[64];
            float b2[32];
            float in[16 * 16];
            float h[16 * 64];
        } m;
        struct {
            float4 ti[16 * 8];
            float4 tj[16 * 8];
        } p;
    } sm;
    __shared__ int s_last;

    int tid = threadIdx.x;
    int bid = blockIdx.x;

    // ================= Phase 1: MLP (producers only) =======================
    if (bid < NMLP) {
        for (int k = tid; k < 16 * 64; k += 256) sm.m.W1[k] = W1[k];
        for (int k = tid; k < 64 * 32; k += 256) sm.m.W2[k] = W2[k];
        if (tid < 64) sm.m.b1[tid] = b1[tid];
        if (tid < 32) sm.m.b2[tid] = b2[tid];
        if (tid < 64) ((float4*)sm.m.in)[tid] = ((const float4*)ape)[bid * 64 + tid];
        __syncthreads();

        int nl = tid >> 4;             // node within group, 0..15
        int p  = tid & 15;
        int n  = bid * 16 + nl;

        // Stage A: hidden values 4p..4p+3 (conflict-free float4 reads)
        float v0 = sm.m.b1[4 * p + 0], v1 = sm.m.b1[4 * p + 1];
        float v2 = sm.m.b1[4 * p + 2], v3 = sm.m.b1[4 * p + 3];
        {
            const float4* w1v = (const float4*)sm.m.W1;
            const float*  ain = sm.m.in + nl * 16;
#pragma unroll
            for (int k = 0; k < 16; k++) {
                float  av = ain[k];
                float4 w  = w1v[k * 16 + p];
                v0 = fmaf(av, w.x, v0);
                v1 = fmaf(av, w.y, v1);
                v2 = fmaf(av, w.z, v2);
                v3 = fmaf(av, w.w, v3);
            }
        }
        float4 hv;
        hv.x = fmaxf(v0, 0.0f); hv.y = fmaxf(v1, 0.0f);
        hv.z = fmaxf(v2, 0.0f); hv.w = fmaxf(v3, 0.0f);
        ((float4*)sm.m.h)[nl * 16 + p] = hv;
        __syncthreads();

        // Stage B: outputs 2p, 2p+1 (conflict-free float2 reads)
        float o0 = sm.m.b2[2 * p + 0], o1 = sm.m.b2[2 * p + 1];
        {
            const float4* h4p = (const float4*)(sm.m.h + nl * 64);
            const float2* w2v = (const float2*)sm.m.W2;
#pragma unroll
            for (int q = 0; q < 16; q++) {
                float4 h4 = h4p[q];
                float2 wa = w2v[(q * 4 + 0) * 16 + p];
                float2 wb = w2v[(q * 4 + 1) * 16 + p];
                float2 wc = w2v[(q * 4 + 2) * 16 + p];
                float2 wd = w2v[(q * 4 + 3) * 16 + p];
                o0 = fmaf(h4.x, wa.x, o0); o1 = fmaf(h4.x, wa.y, o1);
                o0 = fmaf(h4.y, wb.x, o0); o1 = fmaf(h4.y, wb.y, o1);
                o0 = fmaf(h4.z, wc.x, o0); o1 = fmaf(h4.z, wc.y, o1);
                o0 = fmaf(h4.w, wd.x, o0); o1 = fmaf(h4.w, wd.y, o1);
            }
        }
        float2 r2; r2.x = o0; r2.y = o1;
        *(float2*)(g_t + n * 32 + p * 2) = r2;

        // release this group's flag (fence only in the 376 producer blocks)
        __threadfence();
        __syncthreads();               // all g_t stores of the group done
        if (tid == 0) atomicExch(&g_flag[bid], 1);
        __syncthreads();               // union handoff (smem reuse below)
    }

    // ================= Phase 2: this block's pair tile =====================
    int blk = bid;
    int b = 0;
#pragma unroll
    for (int g = 1; g < 16; g++)
        if (blk >= c_tile_start[g]) b = g;

    int lt  = blk - c_tile_start[b];
    int tpr = 16 + b;                  // tiles per row = n_b/16
    int nb  = tpr << 4;                // n_b
    int ti  = lt / tpr;
    int tj  = lt - ti * tpr;
    int ns  = c_node_start[b];
    long long ps = c_pair_start[b];
    int g0  = (ns >> 4) + ti;          // producer group of the i-rows
    int g1  = (ns >> 4) + tj;          // producer group of the j-rows

    // acquire-spin on the two producer flags (no gpu-scope fence / L1 flush)
    if (tid == 0) {
        while (ld_acquire_gpu(&g_flag[g0]) == 0) __nanosleep(20);
    } else if (tid == 1) {
        while (ld_acquire_gpu(&g_flag[g1]) == 0) __nanosleep(20);
    }
    __syncthreads();                   // block-wide: ordered after acquires

    const float4* tp = (const float4*)g_t;
    if (tid < 128) {
        sm.p.ti[tid] = tp[(ns + ti * 16) * 8 + tid];
    } else {
        sm.p.tj[tid - 128] = tp[(ns + tj * 16) * 8 + (tid - 128)];
    }
    __syncthreads();

    float4* op = (float4*)out;
    int l    = tid & 127;              // j*8+q within a 16-row group
    int half = tid >> 7;
    int q    = l & 7;

    float4 vj = sm.p.tj[l];
    long long rowbase = ps + (long long)(ti * 16) * nb + tj * 16;

#pragma unroll
    for (int step = 0; step < 8; step++) {
        int ii = step * 2 + half;
        float4 vi = sm.p.ti[ii * 8 + q];
        float4 v;
        v.x = vi.x + vj.x; v.y = vi.y + vj.y;
        v.z = vi.z + vj.z; v.w = vi.w + vj.w;
        op[(rowbase + (long long)ii * nb) * 8 + l] = v;   // 2KB wavefront
    }

    // ================= Reset state for next replay =========================
    __syncthreads();
    if (tid == 0) {
        s_last = (atomicAdd(&g_done, 1) == NTILE - 1) ? 1 : 0;
    }
    __syncthreads();
    if (s_last) {
        for (int k = tid; k < NMLP; k += 256) g_flag[k] = 0;
        if (tid == 0) atomicExch(&g_done, 0);
    }
}

// ---------------------------------------------------------------------------
extern "C" void kernel_launch(void* const* d_in, const int* in_sizes, int n_in,
                              void* d_out, int out_size) {
    const float* ape = (const float*)d_in[0];
    const float* W1  = (const float*)d_in[1];
    const float* b1  = (const float*)d_in[2];
    const float* W2  = (const float*)d_in[3];
    const float* b2  = (const float*)d_in[4];
    float* out = (float*)d_out;

    fused_kernel<<<NTILE, 256>>>(ape, W1, b1, W2, b2, out);
}

// round 9
// speedup vs baseline: 1.1492x; 1.0046x over previous
#include <cuda_runtime.h>

#define N_TOT 6016
#define NMLP  376          // 16-node groups
#define NTILE 9176

// Static shape tables: sizes g = 256 + 16*g, g in [0,16)
__constant__ int c_node_start[17] = {
    0,256,528,816,1120,1440,1776,2128,2496,2880,3280,3696,4128,4576,5040,5520,6016};
__constant__ long long c_pair_start[17] = {
    0,65536,139520,222464,314880,417280,530176,654080,789504,936960,
    1096960,1270016,1456640,1657344,1872640,2103040,2349056};
__constant__ int c_tile_start[17] = {
    0,256,545,869,1230,1630,2071,2555,3084,3660,4285,4961,5690,6474,7315,8215,9176};

// staged per-node MLP output t[N_TOT][32]
__device__ float g_t[N_TOT * 32];

// per-group ready flags + completion counter (reset in-kernel each launch)
__device__ int g_flag[NMLP];   // zero-initialized
__device__ int g_done = 0;

__device__ __forceinline__ int ld_acquire_gpu(const int* p) {
    int v;
    asm volatile("ld.acquire.gpu.b32 %0, [%1];" : "=r"(v) : "l"(p) : "memory");
    return v;
}

// ---------------------------------------------------------------------------
// Fused single kernel, pair-shaped grid (9176 blocks), 8 blocks/SM.
//   Blocks 0..375: MLP for node group bid (16 nodes, 16 thr/node), SMEM-FREE:
//     weights via coalesced LDG (L1/L2 resident), hidden exchange via
//     width-16 warp shuffles. Release per-group flag.
//   All blocks: pair tile bid; acquire-spin on the 2 producer flags.
// Total smem = 4.1KB -> full L1D for the store stream (key to DRAM%).
// Deadlock-free: launch_bounds(256,8) -> wave 1 = 1184 blocks >= 376 producers.
// ---------------------------------------------------------------------------
__global__ __launch_bounds__(256, 8)
void fused_kernel(const float* __restrict__ ape,
                  const float* __restrict__ W1, const float* __restrict__ b1,
                  const float* __restrict__ W2, const float* __restrict__ b2,
                  float* __restrict__ out) {
    __shared__ float4 s_ti[16 * 8];   // 16 i-rows x 8 float4 (2KB)
    __shared__ float4 s_tj[16 * 8];   // 16 j-rows x 8 float4 (2KB)
    __shared__ int s_last;

    int tid = threadIdx.x;
    int bid = blockIdx.x;

    // ================= Phase 1: MLP (producers only, no smem) ==============
    if (bid < NMLP) {
        int nl = tid >> 4;             // node within group, 0..15
        int p  = tid & 15;
        int n  = bid * 16 + nl;

        const float4* w1v = (const float4*)W1;   // w1v[k*16+p] = W1[k][4p..4p+3]
        const float4* b1v = (const float4*)b1;   // b1v[p]      = b1[4p..4p+3]
        const float2* w2v = (const float2*)W2;   // w2v[h*16+p] = W2[h][2p..2p+1]
        const float2* b2v = (const float2*)b2;   // b2v[p]      = b2[2p..2p+1]
        const float*  ain = ape + n * 16;

        // Stage A: hidden h[4p..4p+3] for node n
        float4 acc = b1v[p];
#pragma unroll
        for (int k = 0; k < 16; k++) {
            float  av = __ldg(ain + k);          // broadcast within group
            float4 w  = w1v[k * 16 + p];         // 256B coalesced per warp
            acc.x = fmaf(av, w.x, acc.x);
            acc.y = fmaf(av, w.y, acc.y);
            acc.z = fmaf(av, w.z, acc.z);
            acc.w = fmaf(av, w.w, acc.w);
        }
        float4 hv;
        hv.x = fmaxf(acc.x, 0.0f); hv.y = fmaxf(acc.y, 0.0f);
        hv.z = fmaxf(acc.z, 0.0f); hv.w = fmaxf(acc.w, 0.0f);

        // Stage B: outputs 2p, 2p+1; gather all 64 h via width-16 shuffles
        float2 o = b2v[p];
#pragma unroll
        for (int q = 0; q < 16; q++) {
            float4 h4;
            h4.x = __shfl_sync(0xffffffffu, hv.x, q, 16);
            h4.y = __shfl_sync(0xffffffffu, hv.y, q, 16);
            h4.z = __shfl_sync(0xffffffffu, hv.z, q, 16);
            h4.w = __shfl_sync(0xffffffffu, hv.w, q, 16);
            float2 wa = w2v[(q * 4 + 0) * 16 + p];   // 128B coalesced per warp
            float2 wb = w2v[(q * 4 + 1) * 16 + p];
            float2 wc = w2v[(q * 4 + 2) * 16 + p];
            float2 wd = w2v[(q * 4 + 3) * 16 + p];
            o.x = fmaf(h4.x, wa.x, o.x); o.y = fmaf(h4.x, wa.y, o.y);
            o.x = fmaf(h4.y, wb.x, o.x); o.y = fmaf(h4.y, wb.y, o.y);
            o.x = fmaf(h4.z, wc.x, o.x); o.y = fmaf(h4.z, wc.y, o.y);
            o.x = fmaf(h4.w, wd.x, o.x); o.y = fmaf(h4.w, wd.y, o.y);
        }
        *(float2*)(g_t + n * 32 + p * 2) = o;    // 2x128B coalesced per warp

        // release this group's flag
        __threadfence();
        __syncthreads();               // all g_t stores of the group done
        if (tid == 0) atomicExch(&g_flag[bid], 1);
    }

    // ================= Phase 2: this block's pair tile =====================
    int blk = bid;
    int b = 0;
#pragma unroll
    for (int g = 1; g < 16; g++)
        if (blk >= c_tile_start[g]) b = g;

    int lt  = blk - c_tile_start[b];
    int tpr = 16 + b;                  // tiles per row = n_b/16
    int nb  = tpr << 4;                // n_b
    int ti  = lt / tpr;
    int tj  = lt - ti * tpr;
    int ns  = c_node_start[b];
    long long ps = c_pair_start[b];
    int g0  = (ns >> 4) + ti;          // producer group of the i-rows
    int g1  = (ns >> 4) + tj;          // producer group of the j-rows

    // acquire-spin on the two producer flags (no gpu-scope fence / L1 flush)
    if (tid == 0) {
        while (ld_acquire_gpu(&g_flag[g0]) == 0) __nanosleep(20);
    } else if (tid == 1) {
        while (ld_acquire_gpu(&g_flag[g1]) == 0) __nanosleep(20);
    }
    __syncthreads();                   // block-wide: ordered after acquires

    const float4* tp = (const float4*)g_t;
    if (tid < 128) {
        s_ti[tid] = tp[(ns + ti * 16) * 8 + tid];
    } else {
        s_tj[tid - 128] = tp[(ns + tj * 16) * 8 + (tid - 128)];
    }
    __syncthreads();

    float4* op = (float4*)out;
    int l    = tid & 127;              // j*8+q within a 16-row group
    int half = tid >> 7;
    int q    = l & 7;

    float4 vj = s_tj[l];
    long long rowbase = ps + (long long)(ti * 16) * nb + tj * 16;

#pragma unroll
    for (int step = 0; step < 8; step++) {
        int ii = step * 2 + half;
        float4 vi = s_ti[ii * 8 + q];
        float4 v;
        v.x = vi.x + vj.x; v.y = vi.y + vj.y;
        v.z = vi.z + vj.z; v.w = vi.w + vj.w;
        op[(rowbase + (long long)ii * nb) * 8 + l] = v;   // 2KB wavefront
    }

    // ================= Reset state for next replay =========================
    __syncthreads();
    if (tid == 0) {
        s_last = (atomicAdd(&g_done, 1) == NTILE - 1) ? 1 : 0;
    }
    __syncthreads();
    if (s_last) {
        for (int k = tid; k < NMLP; k += 256) g_flag[k] = 0;
        if (tid == 0) atomicExch(&g_done, 0);
    }
}

// ---------------------------------------------------------------------------
extern "C" void kernel_launch(void* const* d_in, const int* in_sizes, int n_in,
                              void* d_out, int out_size) {
    const float* ape = (const float*)d_in[0];
    const float* W1  = (const float*)d_in[1];
    const float* b1  = (const float*)d_in[2];
    const float* W2  = (const float*)d_in[3];
    const float* b2  = (const float*)d_in[4];
    float* out = (float*)d_out;

    fused_kernel<<<NTILE, 256>>>(ape, W1, b1, W2, b2, out);
}